// round 13
// baseline (speedup 1.0000x reference)
#include <cuda_runtime.h>
#include <math.h>

// ---------------------------------------------------------------------------
// AttentionLoss, R10 chassis (proven 12.3us) + profiling-parity dummies.
// Launch order per call: k_pre (dummy), k_compute, k_fin, k_post (dummy)
// so ncu's "-s 5 -c 1" capture (6th launch) lands on k_compute.
//   k_compute: each block atomicAdd's its partial into g_parts[blk & 63]
//   k_fin:     64-thread tree reduction of g_parts -> out, then zeroes slots
//   sim  [2,4096,64,64] f32,  wc [2,4096,2] f32 (y,x),  mask [2,64,64] int32
// cwg: blocks 0..1023, 8 warps/block, warp w -> slice blk*8+w,
//      window |dy|,|dx| <= 15.5 (<=32x32), lane = column, 8-batched rows.
// lines: blocks 1024..1087, 4 lines per block (64-thread groups).
// ---------------------------------------------------------------------------

#define BS     2
#define H      64
#define W      64
#define HW     4096
#define NCWG   1024
#define NLBLK  64
#define GRID   (NCWG + NLBLK)
#define NPART  64

#define CWG_SCALE  (-2.0  / 33554432.0)
#define DCML_SCALE (-0.01 / 33554432.0)
#define TV_SCALE   (1.0e-4 / 16128.0)

#define RCUT 15.5f

__device__ double g_parts[NPART];   // static zeros; k_fin re-zeroes each run

__device__ __forceinline__ float warp_sum(float v) {
#pragma unroll
    for (int o = 16; o; o >>= 1) v += __shfl_down_sync(0xffffffffu, v, o);
    return v;
}

// exp(-sqrt(d2)/2), intrinsics only (proven body from R10)
__device__ __forceinline__ float gweight(float d2) {
    d2 = fmaxf(d2, 1e-12f);
    return __expf(-0.5f * (d2 * rsqrtf(d2)));
}

__global__ void k_pre()  {}   // parity dummy
__global__ void k_post() {}   // parity dummy

__global__ void __launch_bounds__(256)
k_compute(const float* __restrict__ sim,
          const float* __restrict__ wc,
          const int*   __restrict__ mask)
{
    int blk  = blockIdx.x;
    int tid  = threadIdx.x;
    int wid  = tid >> 5;
    int lane = tid & 31;

    if (blk < NCWG) {
        // ---------------- cwg: one slice per warp ----------------
        __shared__ float red[8];
        int bp = blk * 8 + wid;
        int mk = mask[bp];                    // warp-uniform

        float acc = 0.0f;
        if (mk) {
            float cy = wc[2 * bp + 0];
            float cx = wc[2 * bp + 1];
            const float* s = sim + (size_t)bp * (size_t)(H * W);

            int iy0 = max(0,     (int)ceilf (cy - RCUT));
            int iy1 = min(H - 1, (int)floorf(cy + RCUT));
            int ix0 = max(0,     (int)ceilf (cx - RCUT));
            int ix1 = min(W - 1, (int)floorf(cx + RCUT));

            int x = ix0 + lane;               // lane = column (<=32 cols)
            if (x <= ix1) {
                float dxsq = ((float)x - cx) * ((float)x - cx);
                const float* p = s + iy0 * W + x;
                int y = iy0;
                for (; y + 7 <= iy1; y += 8, p += 8 * W) {
                    float v0 = p[0*W], v1 = p[1*W], v2 = p[2*W], v3 = p[3*W];
                    float v4 = p[4*W], v5 = p[5*W], v6 = p[6*W], v7 = p[7*W];
                    float fy = (float)y - cy;
                    acc += gweight((fy+0)*(fy+0) + dxsq) * v0;
                    acc += gweight((fy+1)*(fy+1) + dxsq) * v1;
                    acc += gweight((fy+2)*(fy+2) + dxsq) * v2;
                    acc += gweight((fy+3)*(fy+3) + dxsq) * v3;
                    acc += gweight((fy+4)*(fy+4) + dxsq) * v4;
                    acc += gweight((fy+5)*(fy+5) + dxsq) * v5;
                    acc += gweight((fy+6)*(fy+6) + dxsq) * v6;
                    acc += gweight((fy+7)*(fy+7) + dxsq) * v7;
                }
                for (; y <= iy1; ++y, p += W) {
                    float fy = (float)y - cy;
                    acc += gweight(fy * fy + dxsq) * p[0];
                }
            }
        }
        acc = warp_sum(acc);
        if (lane == 0) red[wid] = acc;
        __syncthreads();
        if (tid == 0) {
            float tot = red[0] + red[1] + red[2] + red[3]
                      + red[4] + red[5] + red[6] + red[7];
            atomicAdd(&g_parts[blk & (NPART - 1)], (double)tot * CWG_SCALE);
        }
    } else {
        // ------------- tv + dcml: 4 lines per block -------------
        __shared__ float sy[4][64], sx[4][64], sm[4][64];
        __shared__ float red_dc[8], red_tv[8];

        int grp = tid >> 6;
        int t   = tid & 63;
        int l   = (blk - NCWG) * 4 + grp;
        int b   = l >> 7;
        int dir = (l >> 6) & 1;
        int li  = l & 63;

        int pos = (dir == 0) ? (li * W + t) : (t * W + li);
        int g   = b * HW + pos;
        sy[grp][t] = wc[2 * g + 0];
        sx[grp][t] = wc[2 * g + 1];
        sm[grp][t] = mask[g] ? 1.0f : 0.0f;
        __syncthreads();

        const float* vv = (dir == 0) ? sx[grp] : sy[grp];
        float dc = 0.0f, tv = 0.0f;
        if (sm[grp][t] != 0.0f) {
            float vt = vv[t];
            for (int p = 0; p < t; ++p)
                dc += fmaxf(vt - vv[p], 0.0f) * sm[grp][p];
        }
        if (t < 63) {
            float dy = sy[grp][t + 1] - sy[grp][t];
            float dx = sx[grp][t + 1] - sx[grp][t];
            tv = (dy * dy + dx * dx) * sm[grp][t] * sm[grp][t + 1];
        }
        dc = warp_sum(dc);
        tv = warp_sum(tv);
        if (lane == 0) { red_dc[wid] = dc; red_tv[wid] = tv; }
        __syncthreads();
        if (tid == 0) {
            double tot = 0.0;
#pragma unroll
            for (int q = 0; q < 4; ++q)
                tot += (double)(red_dc[2*q] + red_dc[2*q+1]) * DCML_SCALE
                     + (double)(red_tv[2*q] + red_tv[2*q+1]) * TV_SCALE;
            atomicAdd(&g_parts[blk & (NPART - 1)], tot);
        }
    }
}

// Reduce the 64 partial slots -> out, then zero them for the next replay.
__global__ void __launch_bounds__(64)
k_fin(float* __restrict__ out) {
    __shared__ double sh[NPART];
    int tid = threadIdx.x;
    sh[tid] = g_parts[tid];
    g_parts[tid] = 0.0;                      // restore clean state
    __syncthreads();
#pragma unroll
    for (int o = 32; o > 0; o >>= 1) {
        if (tid < o) sh[tid] += sh[tid + o];
        __syncthreads();
    }
    if (tid == 0) out[0] = (float)sh[0];
}

// ---------------------------------------------------------------------------
extern "C" void kernel_launch(void* const* d_in, const int* in_sizes, int n_in,
                              void* d_out, int out_size) {
    const float* sim  = (const float*)d_in[0];
    const float* wc   = (const float*)d_in[1];
    const int*   mask = (const int*)d_in[2];
    (void)in_sizes; (void)n_in; (void)out_size;

    k_pre    <<<1, 1>>>();
    k_compute<<<GRID, 256>>>(sim, wc, mask);
    k_fin    <<<1, 64>>>((float*)d_out);
    k_post   <<<1, 1>>>();
}

// round 14
// speedup vs baseline: 1.1636x; 1.1636x over previous
#include <cuda_runtime.h>
#include <math.h>

// ---------------------------------------------------------------------------
// AttentionLoss, 2 launches (proven chassis), contention-free atomics.
//   k_compute: blocks 0..1023 cwg (8 warps/block, warp w -> slice blk*8+w),
//              blocks 1024..1087 tv/dcml lines (4 per block).
//              Partials -> atomicAdd g_parts[blk & 63].
//   k_fin:     64-thread tree reduction of g_parts -> out, zeroes slots.
//   sim  [2,4096,64,64] f32,  wc [2,4096,2] f32 (y,x),  mask [2,64,64] int32
// cwg inner loop (float2 scheme):
//   window |dy|,|dx| <= 15 -> <=31 cols; left edge aligned down to even ->
//   <=16 float2 pairs. lane = (h = lane>>4 row-half, k = lane&15 pair).
//   Each iteration covers rows (y+h) for 2 rows; batches of 4 iterations
//   keep 4 LDG.64 in flight per lane. Extra cols/rows read inside the slice
//   are valid superset terms (reduce windowing error).
// ---------------------------------------------------------------------------

#define BS     2
#define H      64
#define W      64
#define HW     4096
#define NCWG   1024
#define NLBLK  64
#define GRID   (NCWG + NLBLK)
#define NPART  64

#define CWG_SCALE  (-2.0  / 33554432.0)
#define DCML_SCALE (-0.01 / 33554432.0)
#define TV_SCALE   (1.0e-4 / 16128.0)

#define RCUT 15.0f

__device__ double g_parts[NPART];   // static zeros; k_fin re-zeroes each run

__device__ __forceinline__ float warp_sum(float v) {
#pragma unroll
    for (int o = 16; o; o >>= 1) v += __shfl_down_sync(0xffffffffu, v, o);
    return v;
}

// exp(-sqrt(d2)/2), intrinsics (proven body)
__device__ __forceinline__ float gweight(float d2) {
    d2 = fmaxf(d2, 1e-12f);
    return __expf(-0.5f * (d2 * rsqrtf(d2)));
}

__global__ void __launch_bounds__(256)
k_compute(const float* __restrict__ sim,
          const float* __restrict__ wc,
          const int*   __restrict__ mask)
{
    int blk  = blockIdx.x;
    int tid  = threadIdx.x;
    int wid  = tid >> 5;
    int lane = tid & 31;

    if (blk < NCWG) {
        // ---------------- cwg: one slice per warp ----------------
        __shared__ float red[8];
        int bp = blk * 8 + wid;
        int mk = mask[bp];                    // warp-uniform

        float acc = 0.0f;
        if (mk) {
            float cy = wc[2 * bp + 0];
            float cx = wc[2 * bp + 1];
            const float* s = sim + (size_t)bp * (size_t)(H * W);

            int iy0 = max(0,     (int)ceilf (cy - RCUT));
            int iy1 = min(H - 1, (int)floorf(cy + RCUT));
            int ix0 = max(0,     (int)ceilf (cx - RCUT));
            int ix1 = min(W - 1, (int)floorf(cx + RCUT));

            int h = lane >> 4;                // row-half: 0 or 1
            int k = lane & 15;                // column-pair index
            int x = (ix0 & ~1) + 2 * k;       // even -> 8B-aligned float2

            if (x <= ix1) {                   // active column pair
                float dxa = (float)x       - cx;
                float dxb = (float)(x + 1) - cx;
                float dxa2 = dxa * dxa;
                float dxb2 = dxb * dxb;

                const float* p = s + (iy0 + h) * W + x;   // this lane's row
                int y = iy0;
                // batch: 4 row-pairs = rows y..y+7 (this lane: y+h, +2, +4, +6)
                for (; y + 6 <= iy1; y += 8, p += 8 * W) {
                    int r3ok = (y + 6 + h) <= (H - 1);    // only last can exceed 63
                    float2 v0 = *(const float2*)(p);
                    float2 v1 = *(const float2*)(p + 2 * W);
                    float2 v2 = *(const float2*)(p + 4 * W);
                    float2 v3 = r3ok ? *(const float2*)(p + 6 * W)
                                     : make_float2(0.f, 0.f);
                    float fy = (float)(y + h) - cy;
                    float f0 = fy,     f1 = fy + 2.f;
                    float f2 = fy + 4.f, f3 = fy + 6.f;
                    acc += gweight(fmaf(f0, f0, dxa2)) * v0.x
                         + gweight(fmaf(f0, f0, dxb2)) * v0.y;
                    acc += gweight(fmaf(f1, f1, dxa2)) * v1.x
                         + gweight(fmaf(f1, f1, dxb2)) * v1.y;
                    acc += gweight(fmaf(f2, f2, dxa2)) * v2.x
                         + gweight(fmaf(f2, f2, dxb2)) * v2.y;
                    acc += gweight(fmaf(f3, f3, dxa2)) * v3.x
                         + gweight(fmaf(f3, f3, dxb2)) * v3.y;
                }
                // tail: single row-pairs
                for (; y <= iy1; y += 2, p += 2 * W) {
                    int row = y + h;
                    if (row <= H - 1) {
                        float2 v = *(const float2*)(p);
                        float fy = (float)row - cy;
                        acc += gweight(fmaf(fy, fy, dxa2)) * v.x
                             + gweight(fmaf(fy, fy, dxb2)) * v.y;
                    }
                }
            }
        }
        acc = warp_sum(acc);
        if (lane == 0) red[wid] = acc;
        __syncthreads();
        if (tid == 0) {
            float tot = red[0] + red[1] + red[2] + red[3]
                      + red[4] + red[5] + red[6] + red[7];
            atomicAdd(&g_parts[blk & (NPART - 1)], (double)tot * CWG_SCALE);
        }
    } else {
        // ------------- tv + dcml: 4 lines per block -------------
        __shared__ float sy[4][64], sx[4][64], sm[4][64];
        __shared__ float red_dc[8], red_tv[8];

        int grp = tid >> 6;
        int t   = tid & 63;
        int l   = (blk - NCWG) * 4 + grp;
        int b   = l >> 7;
        int dir = (l >> 6) & 1;
        int li  = l & 63;

        int pos = (dir == 0) ? (li * W + t) : (t * W + li);
        int g   = b * HW + pos;
        sy[grp][t] = wc[2 * g + 0];
        sx[grp][t] = wc[2 * g + 1];
        sm[grp][t] = mask[g] ? 1.0f : 0.0f;
        __syncthreads();

        const float* vv = (dir == 0) ? sx[grp] : sy[grp];
        float dc = 0.0f, tv = 0.0f;
        if (sm[grp][t] != 0.0f) {
            float vt = vv[t];
            for (int p = 0; p < t; ++p)
                dc += fmaxf(vt - vv[p], 0.0f) * sm[grp][p];
        }
        if (t < 63) {
            float dy = sy[grp][t + 1] - sy[grp][t];
            float dx = sx[grp][t + 1] - sx[grp][t];
            tv = (dy * dy + dx * dx) * sm[grp][t] * sm[grp][t + 1];
        }
        dc = warp_sum(dc);
        tv = warp_sum(tv);
        if (lane == 0) { red_dc[wid] = dc; red_tv[wid] = tv; }
        __syncthreads();
        if (tid == 0) {
            double tot = 0.0;
#pragma unroll
            for (int q = 0; q < 4; ++q)
                tot += (double)(red_dc[2*q] + red_dc[2*q+1]) * DCML_SCALE
                     + (double)(red_tv[2*q] + red_tv[2*q+1]) * TV_SCALE;
            atomicAdd(&g_parts[blk & (NPART - 1)], tot);
        }
    }
}

// Reduce the 64 partial slots -> out, then zero them for the next replay.
__global__ void __launch_bounds__(64)
k_fin(float* __restrict__ out) {
    __shared__ double sh[NPART];
    int tid = threadIdx.x;
    sh[tid] = g_parts[tid];
    g_parts[tid] = 0.0;                      // restore clean state
    __syncthreads();
#pragma unroll
    for (int o = 32; o > 0; o >>= 1) {
        if (tid < o) sh[tid] += sh[tid + o];
        __syncthreads();
    }
    if (tid == 0) out[0] = (float)sh[0];
}

// ---------------------------------------------------------------------------
extern "C" void kernel_launch(void* const* d_in, const int* in_sizes, int n_in,
                              void* d_out, int out_size) {
    const float* sim  = (const float*)d_in[0];
    const float* wc   = (const float*)d_in[1];
    const int*   mask = (const int*)d_in[2];
    (void)in_sizes; (void)n_in; (void)out_size;

    k_compute<<<GRID, 256>>>(sim, wc, mask);
    k_fin    <<<1, 64>>>((float*)d_out);
}